// round 11
// baseline (speedup 1.0000x reference)
#include <cuda_runtime.h>
#include <math_constants.h>

// Problem constants (FeatureAttention: N=500000, C=256, R=4, B=1024)
#define BSEG 1024
#define CCH  256
#define C4   64      // C/4 float4s per row
#define HID  64      // C/R
#define NSM  152     // GB300 SM count (persistent grid)
#define TPB  1024
#define RG   16      // row-groups per CTA (TPB/64)
#define UNR  8       // load-unroll depth (rows per thread per iteration)

// Scratch (no dynamic allocation allowed)
__device__ int g_seg_start[BSEG + 1];

// batch may arrive as int32 (JAX x64-off) or int64 (as declared). Sorted,
// values in [0,1024). If int64 (LE), slot [n-1] (odd 32-bit index) is a zero
// high-word; if int32, slot [n-1] is the max segment id (>0 w.p. ~1).
__device__ __forceinline__ int load_batch(const int* __restrict__ b32, bool is64, int i) {
    return is64 ? b32[2 * i] : b32[i];
}

// ---------------------------------------------------------------------------
// Kernel 1: segment boundaries via streaming adjacent-diff (batch is sorted).
// ---------------------------------------------------------------------------
__global__ void seg_bounds_kernel(const int* __restrict__ b32, int n) {
    int i = blockIdx.x * blockDim.x + threadIdx.x;
    if (i >= n) return;
    bool is64 = (b32[n - 1] == 0);
    int v    = load_batch(b32, is64, i);
    int prev = (i == 0) ? -1 : load_batch(b32, is64, i - 1);
    for (int b = prev + 1; b <= v; b++) g_seg_start[b] = i;
    if (i == n - 1)
        for (int b = v + 1; b <= BSEG; b++) g_seg_start[b] = n;
}

// ---------------------------------------------------------------------------
// Kernel 2 (fused, persistent): per-segment sum+max reduce -> bottleneck MLP
// -> gate pass over the same rows (L2-hot second read).
// 1024 threads = 64 float4 lanes x 16 row-groups; 8-deep load unroll
// (128 rows per CTA iteration) for ~256 in-flight lines per SM.
// ---------------------------------------------------------------------------
__global__ void __launch_bounds__(TPB, 1) fused_kernel(
    const float4* __restrict__ x4,
    const float*  __restrict__ w1,   // [C, H] row-major
    const float*  __restrict__ w2,   // [H, C] row-major
    float4*       __restrict__ out4)
{
    __shared__ __align__(16) float4 rs[RG][C4];
    __shared__ __align__(16) float4 rm[RG][C4];
    __shared__ __align__(16) float  s_sum[CCH];
    __shared__ __align__(16) float  s_max[CCH];
    __shared__ float s_h[2 * HID];
    __shared__ __align__(16) float4 s_y[C4];

    const int tid = threadIdx.x;
    const int c4  = tid & 63;
    const int rg  = tid >> 6;          // 0..15

    for (int b = blockIdx.x; b < BSEG; b += gridDim.x) {
        const int start = g_seg_start[b];
        const int end   = g_seg_start[b + 1];
        if (end == start) continue;     // empty segment: nothing to reduce/write

        // ---- pass 1: sum + max; UNR independent loads per thread per iter ----
        float4 s = make_float4(0.f, 0.f, 0.f, 0.f);
        float4 m = make_float4(-CUDART_INF_F, -CUDART_INF_F, -CUDART_INF_F, -CUDART_INF_F);
        int base = start;
        for (; base + UNR * RG <= end; base += UNR * RG) {
            const float4* p = x4 + (long long)(base + rg) * C4 + c4;
            float4 v[UNR];
            #pragma unroll
            for (int u = 0; u < UNR; u++) v[u] = p[u * RG * C4];   // 8 LDG.128 issued back-to-back
            #pragma unroll
            for (int u = 0; u < UNR; u++) {
                s.x += v[u].x; s.y += v[u].y; s.z += v[u].z; s.w += v[u].w;
                m.x = fmaxf(m.x, v[u].x); m.y = fmaxf(m.y, v[u].y);
                m.z = fmaxf(m.z, v[u].z); m.w = fmaxf(m.w, v[u].w);
            }
        }
        for (int r = base + rg; r < end; r += RG) {
            float4 v = x4[(long long)r * C4 + c4];
            s.x += v.x; s.y += v.y; s.z += v.z; s.w += v.w;
            m.x = fmaxf(m.x, v.x); m.y = fmaxf(m.y, v.y);
            m.z = fmaxf(m.z, v.z); m.w = fmaxf(m.w, v.w);
        }
        rs[rg][c4] = s;
        rm[rg][c4] = m;
        __syncthreads();

        if (rg == 0) {
            float4 a  = rs[0][c4];
            float4 mm = rm[0][c4];
            #pragma unroll
            for (int g = 1; g < RG; g++) {
                float4 t = rs[g][c4];
                a.x += t.x; a.y += t.y; a.z += t.z; a.w += t.w;
                float4 u = rm[g][c4];
                mm.x = fmaxf(mm.x, u.x); mm.y = fmaxf(mm.y, u.y);
                mm.z = fmaxf(mm.z, u.z); mm.w = fmaxf(mm.w, u.w);
            }
            reinterpret_cast<float4*>(s_sum)[c4] = a;
            reinterpret_cast<float4*>(s_max)[c4] = mm;
        }
        __syncthreads();

        // ---- MLP stage 1: hidden = relu(pooled @ w1); 4 accumulators ----
        if (tid < 128) {
            const int j = tid & 63;
            const float* src = (tid < 64) ? s_sum : s_max;
            float a0 = 0.f, a1 = 0.f, a2 = 0.f, a3 = 0.f;
            #pragma unroll
            for (int k = 0; k < CCH; k += 4) {
                a0 = fmaf(src[k + 0], w1[(k + 0) * HID + j], a0);
                a1 = fmaf(src[k + 1], w1[(k + 1) * HID + j], a1);
                a2 = fmaf(src[k + 2], w1[(k + 2) * HID + j], a2);
                a3 = fmaf(src[k + 3], w1[(k + 3) * HID + j], a3);
            }
            s_h[tid] = fmaxf((a0 + a1) + (a2 + a3), 0.f);
        }
        __syncthreads();

        // ---- MLP stage 2: y = relu((h_sum + h_max) @ w2); 2 accumulators ----
        if (tid < CCH) {
            float a0 = 0.f, a1 = 0.f;
            #pragma unroll
            for (int j = 0; j < HID; j += 2) {
                a0 = fmaf(s_h[j]     + s_h[HID + j],     w2[(j)     * CCH + tid], a0);
                a1 = fmaf(s_h[j + 1] + s_h[HID + j + 1], w2[(j + 1) * CCH + tid], a1);
            }
            ((float*)s_y)[tid] = fmaxf(a0 + a1, 0.f);
        }
        __syncthreads();

        // ---- pass 2: gate same rows (L2-hot read), UNR-deep, WT stores ----
        const float4 yv = s_y[c4];
        base = start;
        for (; base + UNR * RG <= end; base += UNR * RG) {
            const float4* p = x4   + (long long)(base + rg) * C4 + c4;
            float4*       q = out4 + (long long)(base + rg) * C4 + c4;
            float4 v[UNR];
            #pragma unroll
            for (int u = 0; u < UNR; u++) v[u] = __ldcs(&p[u * RG * C4]);
            #pragma unroll
            for (int u = 0; u < UNR; u++)
                __stwt(&q[u * RG * C4],
                       make_float4(v[u].x * yv.x, v[u].y * yv.y, v[u].z * yv.z, v[u].w * yv.w));
        }
        for (int r = base + rg; r < end; r += RG) {
            float4 xv = __ldcs(&x4[(long long)r * C4 + c4]);
            __stwt(&out4[(long long)r * C4 + c4],
                   make_float4(xv.x * yv.x, xv.y * yv.y, xv.z * yv.z, xv.w * yv.w));
        }
        __syncthreads();   // protect smem before next segment iteration
    }
}

// ---------------------------------------------------------------------------
extern "C" void kernel_launch(void* const* d_in, const int* in_sizes, int n_in,
                              void* d_out, int out_size) {
    // metadata order: x [N*C] f32, batch [N] int, w1 [C*H] f32, w2 [H*C] f32
    const float* x     = (const float*)d_in[0];
    const int*   batch = (const int*)d_in[1];
    const float* w1    = (const float*)d_in[2];
    const float* w2    = (const float*)d_in[3];
    const int n = in_sizes[1];

    seg_bounds_kernel<<<(n + 255) / 256, 256>>>(batch, n);
    fused_kernel<<<NSM, TPB>>>((const float4*)x, w1, w2, (float4*)d_out);
}

// round 12
// speedup vs baseline: 1.0269x; 1.0269x over previous
#include <cuda_runtime.h>
#include <math_constants.h>

// Problem constants (FeatureAttention: N=500000, C=256, R=4, B=1024)
#define BSEG 1024
#define CCH  256
#define C4   64      // C/4 float4s per row
#define HID  64      // C/R
#define NSM  152     // GB300 SM count (persistent grid)
#define TPB  512     // 512 threads => 128 regs/thread budget (deep load staging)
#define RG   8       // row-groups per CTA (TPB/64)
#define UNR  16      // load-unroll depth (rows per thread per iteration)

// Scratch (no dynamic allocation allowed)
__device__ int g_seg_start[BSEG + 1];

// batch may arrive as int32 (JAX x64-off) or int64 (as declared). Sorted,
// values in [0,1024). If int64 (LE), slot [n-1] (odd 32-bit index) is a zero
// high-word; if int32, slot [n-1] is the max segment id (>0 w.p. ~1).
__device__ __forceinline__ int load_batch(const int* __restrict__ b32, bool is64, int i) {
    return is64 ? b32[2 * i] : b32[i];
}

// ---------------------------------------------------------------------------
// Kernel 1: segment boundaries via streaming adjacent-diff (batch is sorted).
// ---------------------------------------------------------------------------
__global__ void seg_bounds_kernel(const int* __restrict__ b32, int n) {
    int i = blockIdx.x * blockDim.x + threadIdx.x;
    if (i >= n) return;
    bool is64 = (b32[n - 1] == 0);
    int v    = load_batch(b32, is64, i);
    int prev = (i == 0) ? -1 : load_batch(b32, is64, i - 1);
    for (int b = prev + 1; b <= v; b++) g_seg_start[b] = i;
    if (i == n - 1)
        for (int b = v + 1; b <= BSEG; b++) g_seg_start[b] = n;
}

// ---------------------------------------------------------------------------
// Kernel 2 (fused, persistent): per-segment sum+max reduce -> bottleneck MLP
// -> gate pass over the same rows (L2-hot second read).
// 512 threads = 64 float4 lanes x 8 row-groups; 16-deep register-staged load
// unroll (128 rows per CTA iteration) => ~256 in-flight lines per SM.
// ---------------------------------------------------------------------------
__global__ void __launch_bounds__(TPB, 1) fused_kernel(
    const float4* __restrict__ x4,
    const float*  __restrict__ w1,   // [C, H] row-major
    const float*  __restrict__ w2,   // [H, C] row-major
    float4*       __restrict__ out4)
{
    __shared__ __align__(16) float4 rs[RG][C4];
    __shared__ __align__(16) float4 rm[RG][C4];
    __shared__ __align__(16) float  s_sum[CCH];
    __shared__ __align__(16) float  s_max[CCH];
    __shared__ float s_h[2 * HID];
    __shared__ __align__(16) float4 s_y[C4];

    const int tid = threadIdx.x;
    const int c4  = tid & 63;
    const int rg  = tid >> 6;          // 0..7

    for (int b = blockIdx.x; b < BSEG; b += gridDim.x) {
        const int start = g_seg_start[b];
        const int end   = g_seg_start[b + 1];
        if (end == start) continue;     // empty segment: nothing to reduce/write

        // ---- pass 1: sum + max; UNR register-staged loads per iteration ----
        float4 s = make_float4(0.f, 0.f, 0.f, 0.f);
        float4 m = make_float4(-CUDART_INF_F, -CUDART_INF_F, -CUDART_INF_F, -CUDART_INF_F);
        int base = start;
        for (; base + UNR * RG <= end; base += UNR * RG) {
            const float4* p = x4 + (long long)(base + rg) * C4 + c4;
            float4 v[UNR];
            #pragma unroll
            for (int u = 0; u < UNR; u++) v[u] = p[u * RG * C4];   // 16 LDG.128 front-batched
            #pragma unroll
            for (int u = 0; u < UNR; u++) {
                s.x += v[u].x; s.y += v[u].y; s.z += v[u].z; s.w += v[u].w;
                m.x = fmaxf(m.x, v[u].x); m.y = fmaxf(m.y, v[u].y);
                m.z = fmaxf(m.z, v[u].z); m.w = fmaxf(m.w, v[u].w);
            }
        }
        for (int r = base + rg; r < end; r += RG) {
            float4 v = x4[(long long)r * C4 + c4];
            s.x += v.x; s.y += v.y; s.z += v.z; s.w += v.w;
            m.x = fmaxf(m.x, v.x); m.y = fmaxf(m.y, v.y);
            m.z = fmaxf(m.z, v.z); m.w = fmaxf(m.w, v.w);
        }
        rs[rg][c4] = s;
        rm[rg][c4] = m;
        __syncthreads();

        if (rg == 0) {
            float4 a  = rs[0][c4];
            float4 mm = rm[0][c4];
            #pragma unroll
            for (int g = 1; g < RG; g++) {
                float4 t = rs[g][c4];
                a.x += t.x; a.y += t.y; a.z += t.z; a.w += t.w;
                float4 u = rm[g][c4];
                mm.x = fmaxf(mm.x, u.x); mm.y = fmaxf(mm.y, u.y);
                mm.z = fmaxf(mm.z, u.z); mm.w = fmaxf(mm.w, u.w);
            }
            reinterpret_cast<float4*>(s_sum)[c4] = a;
            reinterpret_cast<float4*>(s_max)[c4] = mm;
        }
        __syncthreads();

        // ---- MLP stage 1: hidden = relu(pooled @ w1); 4 accumulators ----
        if (tid < 128) {
            const int j = tid & 63;
            const float* src = (tid < 64) ? s_sum : s_max;
            float a0 = 0.f, a1 = 0.f, a2 = 0.f, a3 = 0.f;
            #pragma unroll
            for (int k = 0; k < CCH; k += 4) {
                a0 = fmaf(src[k + 0], w1[(k + 0) * HID + j], a0);
                a1 = fmaf(src[k + 1], w1[(k + 1) * HID + j], a1);
                a2 = fmaf(src[k + 2], w1[(k + 2) * HID + j], a2);
                a3 = fmaf(src[k + 3], w1[(k + 3) * HID + j], a3);
            }
            s_h[tid] = fmaxf((a0 + a1) + (a2 + a3), 0.f);
        }
        __syncthreads();

        // ---- MLP stage 2: y = relu((h_sum + h_max) @ w2); 2 accumulators ----
        if (tid < CCH) {
            float a0 = 0.f, a1 = 0.f;
            #pragma unroll
            for (int j = 0; j < HID; j += 2) {
                a0 = fmaf(s_h[j]     + s_h[HID + j],     w2[(j)     * CCH + tid], a0);
                a1 = fmaf(s_h[j + 1] + s_h[HID + j + 1], w2[(j + 1) * CCH + tid], a1);
            }
            ((float*)s_y)[tid] = fmaxf(a0 + a1, 0.f);
        }
        __syncthreads();

        // ---- pass 2: gate same rows (L2-hot read), UNR-deep, WT stores ----
        const float4 yv = s_y[c4];
        base = start;
        for (; base + UNR * RG <= end; base += UNR * RG) {
            const float4* p = x4   + (long long)(base + rg) * C4 + c4;
            float4*       q = out4 + (long long)(base + rg) * C4 + c4;
            float4 v[UNR];
            #pragma unroll
            for (int u = 0; u < UNR; u++) v[u] = __ldcs(&p[u * RG * C4]);
            #pragma unroll
            for (int u = 0; u < UNR; u++)
                __stwt(&q[u * RG * C4],
                       make_float4(v[u].x * yv.x, v[u].y * yv.y, v[u].z * yv.z, v[u].w * yv.w));
        }
        for (int r = base + rg; r < end; r += RG) {
            float4 xv = __ldcs(&x4[(long long)r * C4 + c4]);
            __stwt(&out4[(long long)r * C4 + c4],
                   make_float4(xv.x * yv.x, xv.y * yv.y, xv.z * yv.z, xv.w * yv.w));
        }
        __syncthreads();   // protect smem before next segment iteration
    }
}

// ---------------------------------------------------------------------------
extern "C" void kernel_launch(void* const* d_in, const int* in_sizes, int n_in,
                              void* d_out, int out_size) {
    // metadata order: x [N*C] f32, batch [N] int, w1 [C*H] f32, w2 [H*C] f32
    const float* x     = (const float*)d_in[0];
    const int*   batch = (const int*)d_in[1];
    const float* w1    = (const float*)d_in[2];
    const float* w2    = (const float*)d_in[3];
    const int n = in_sizes[1];

    seg_bounds_kernel<<<(n + 255) / 256, 256>>>(batch, n);
    fused_kernel<<<NSM, TPB>>>((const float4*)x, w1, w2, (float4*)d_out);
}